// round 7
// baseline (speedup 1.0000x reference)
#include <cuda_runtime.h>
#include <cuda_bf16.h>
#include <cstdint>

#define NEXP 64
#define KDIM 1024
#define NROWS 131072
#define HIGH_NEG -100000.0f
#define CRANK0 98303u

// ---------------- scratch ----------------
#define NBINS 8192               // 13-bit level-1 histogram
#define CAP 8192                 // candidate capacity per expert
__device__ uint32_t g_hist1[NEXP * NBINS];
__device__ uint32_t g_cand[NEXP * CAP];
__device__ uint32_t g_cnt[NEXP];
__device__ uint32_t g_minb1[NEXP];
__device__ uint32_t g_bkt0[NEXP], g_rnk0[NEXP], g_bkt1[NEXP], g_rnk1[NEXP];
__device__ float    g_tcol[NEXP];
__device__ __nv_bfloat16 g_whi[NEXP * KDIM];
__device__ __nv_bfloat16 g_wlo[NEXP * KDIM];

// ---------------- helpers ----------------
__device__ __forceinline__ uint32_t f2o(float f) {
    uint32_t u = __float_as_uint(f);
    return u ^ ((u & 0x80000000u) ? 0xFFFFFFFFu : 0x80000000u);
}
__device__ __forceinline__ float o2f(uint32_t u) {
    u ^= ((u & 0x80000000u) ? 0x80000000u : 0xFFFFFFFFu);
    return __uint_as_float(u);
}
__device__ __forceinline__ uint32_t smem_u32(const void* p) {
    uint32_t a;
    asm("{ .reg .u64 t; cvta.to.shared.u64 t, %1; cvt.u32.u64 %0, t; }" : "=r"(a) : "l"(p));
    return a;
}
__device__ __forceinline__ void ldmx4(uint32_t* r, uint32_t addr) {
    asm volatile("ldmatrix.sync.aligned.m8n8.x4.shared.b16 {%0,%1,%2,%3}, [%4];"
                 : "=r"(r[0]), "=r"(r[1]), "=r"(r[2]), "=r"(r[3]) : "r"(addr));
}
__device__ __forceinline__ void mma_bf16(float* d, const uint32_t* a,
                                         uint32_t b0, uint32_t b1) {
    asm volatile(
        "mma.sync.aligned.m16n8k16.row.col.f32.bf16.bf16.f32 "
        "{%0,%1,%2,%3}, {%4,%5,%6,%7}, {%8,%9}, {%0,%1,%2,%3};"
        : "+f"(d[0]), "+f"(d[1]), "+f"(d[2]), "+f"(d[3])
        : "r"(a[0]), "r"(a[1]), "r"(a[2]), "r"(a[3]), "r"(b0), "r"(b1));
}
__device__ __forceinline__ void cpasync16(uint32_t dst, const void* src) {
    asm volatile("cp.async.cg.shared.global [%0], [%1], 16;"
                 :: "r"(dst), "l"(src) : "memory");
}
__device__ __forceinline__ uint32_t warp_iscan(uint32_t v, int lane) {
#pragma unroll
    for (int o = 1; o < 32; o <<= 1) {
        uint32_t t = __shfl_up_sync(0xffffffffu, v, o);
        if (lane >= o) v += t;
    }
    return v;
}

// ---------------- launch idx 0: zero hist1 ----------------
__global__ void zero_hist1() {
    uint4* a = reinterpret_cast<uint4*>(g_hist1);
    int i = blockIdx.x * blockDim.x + threadIdx.x;
    a[i] = make_uint4(0u, 0u, 0u, 0u);
}

// ---------------- launch idx 1: W -> bf16 hi/lo ----------------
__global__ void w_convert(const float* __restrict__ W) {
    int i = blockIdx.x * blockDim.x + threadIdx.x;
    float v = W[i];
    __nv_bfloat16 h = __float2bfloat16(v);
    g_whi[i] = h;
    g_wlo[i] = __float2bfloat16(v - __bfloat162float(h));
}

// ---------------- launch idx 2: small inits ----------------
__global__ void init_small() {
    if (threadIdx.x < NEXP) {
        g_cnt[threadIdx.x] = 0u;
        g_minb1[threadIdx.x] = 0xFFFFFFFFu;
    }
}

// ---------------- launch idx 3: 4-CTA/SM BM=64 mma GEMM ----------------------
#define BM 64
#define NTHR 128
#define CHUNK 64
#define NCH (KDIM / CHUNK)
// smem layout per CTA (48 KB):
#define STAG 0                           // 16 KB fp32 staging (single)
#define SM_A_HI 16384                    // 64 x 128B swizzled bf16
#define SM_A_LO 24576
#define SM_B_HI 32768
#define SM_B_LO 40960
#define SMEM_TOTAL 49152
#define STGW 68

__global__ __launch_bounds__(NTHR, 4) void gemm_mma(
    const float* __restrict__ x, const float* __restrict__ bias,
    const float* __restrict__ noise, float* __restrict__ out)
{
    extern __shared__ char smem[];
    const uint32_t sb = smem_u32(smem);
    const int tid = threadIdx.x;
    const int wid = tid >> 5, lid = tid & 31;
    const int rowBase = blockIdx.x * BM;
    const float* xr = x + (size_t)rowBase * KDIM;

    float acc[8][4];
#pragma unroll
    for (int ni = 0; ni < 8; ni++)
#pragma unroll
        for (int j = 0; j < 4; j++) acc[ni][j] = 0.0f;

    // ldmatrix addressing (swizzled 128B rows; (row&7)==(lid&7) for both A and B)
    const uint32_t amask = (uint32_t)((lid & 7) << 4);
    const uint32_t asel = (uint32_t)((lid >> 4) * 16);
    const uint32_t aBaseH = sb + SM_A_HI + (uint32_t)(wid * 16 + (lid & 15)) * 128;
    const uint32_t aBaseL = aBaseH + (SM_A_LO - SM_A_HI);
    const uint32_t bsel = (uint32_t)(((lid >> 3) & 1) * 16);
    const uint32_t bBaseH = sb + SM_B_HI +
        (uint32_t)(((lid >> 4) << 3) + (lid & 7)) * 128;
    const uint32_t bBaseL = bBaseH + (SM_B_LO - SM_B_HI);

    // ---- convert helper is inlined twice (prologue + loop) via lambda ----
    auto do_convert = [&](int kc) {
        // A: staging fp32 (64 x 256B) -> hi/lo bf16 swizzled
#pragma unroll
        for (int i = 0; i < 8; i++) {
            int l = tid + i * NTHR;
            int r = l >> 4, q = l & 15;
            float4 v = *reinterpret_cast<const float4*>(smem + STAG + r * 256 + q * 16);
            uint32_t h01, h23, l01, l23;
            asm("cvt.rn.bf16x2.f32 %0, %1, %2;" : "=r"(h01) : "f"(v.y), "f"(v.x));
            asm("cvt.rn.bf16x2.f32 %0, %1, %2;" : "=r"(h23) : "f"(v.w), "f"(v.z));
            float r0 = v.x - __uint_as_float(h01 << 16);
            float r1 = v.y - __uint_as_float(h01 & 0xFFFF0000u);
            float r2 = v.z - __uint_as_float(h23 << 16);
            float r3 = v.w - __uint_as_float(h23 & 0xFFFF0000u);
            asm("cvt.rn.bf16x2.f32 %0, %1, %2;" : "=r"(l01) : "f"(r1), "f"(r0));
            asm("cvt.rn.bf16x2.f32 %0, %1, %2;" : "=r"(l23) : "f"(r3), "f"(r2));
            uint32_t off = (uint32_t)(r * 128) +
                           (((uint32_t)(q * 8)) ^ ((uint32_t)((r & 7) << 4)));
            *reinterpret_cast<uint2*>(smem + SM_A_HI + off) = make_uint2(h01, h23);
            *reinterpret_cast<uint2*>(smem + SM_A_LO + off) = make_uint2(l01, l23);
        }
        // B: preconverted W hi/lo from gmem(L2) -> swizzled
        const uint4* wh = reinterpret_cast<const uint4*>(g_whi);
        const uint4* wl = reinterpret_cast<const uint4*>(g_wlo);
#pragma unroll
        for (int i = 0; i < 4; i++) {
            int l = tid + i * NTHR;
            int e = l >> 3, q = l & 7;
            uint32_t src = (uint32_t)(e * KDIM + kc) >> 3;
            uint32_t off = (uint32_t)(e * 128) +
                           (((uint32_t)(q * 16)) ^ ((uint32_t)((e & 7) << 4)));
            *reinterpret_cast<uint4*>(smem + SM_B_HI + off) = wh[src + q];
            *reinterpret_cast<uint4*>(smem + SM_B_LO + off) = wl[src + q];
        }
    };
    auto issue_cp = [&](int kc) {
#pragma unroll
        for (int i = 0; i < 8; i++) {
            int l = tid + i * NTHR;
            int r = l >> 4, q = l & 15;
            cpasync16(sb + STAG + (uint32_t)(r * 256 + q * 16),
                      xr + (size_t)r * KDIM + kc + q * 4);
        }
        asm volatile("cp.async.commit_group;" ::: "memory");
    };

    // ---- prologue ----
    issue_cp(0);
    asm volatile("cp.async.wait_group 0;" ::: "memory");
    __syncthreads();
    do_convert(0);
    __syncthreads();
    issue_cp(CHUNK);

    for (int c = 0; c < NCH; c++) {
        // ---- mma over tiles (chunk c) ----
#pragma unroll
        for (int kk = 0; kk < 4; kk++) {
            const uint32_t ca = (asel + (uint32_t)(kk * 32)) ^ amask;
            const uint32_t cb = (bsel + (uint32_t)(kk * 32)) ^ amask;
            uint32_t ah[4], al[4];
            ldmx4(ah, aBaseH + ca);
            ldmx4(al, aBaseL + ca);
#pragma unroll
            for (int g = 0; g < 4; g++) {
                uint32_t bh[4], bl[4];
                ldmx4(bh, bBaseH + (uint32_t)(g * 2048) + cb);
                ldmx4(bl, bBaseL + (uint32_t)(g * 2048) + cb);
                mma_bf16(acc[2 * g],     ah, bh[0], bh[1]);
                mma_bf16(acc[2 * g],     ah, bl[0], bl[1]);
                mma_bf16(acc[2 * g],     al, bh[0], bh[1]);
                mma_bf16(acc[2 * g + 1], ah, bh[2], bh[3]);
                mma_bf16(acc[2 * g + 1], ah, bl[2], bl[3]);
                mma_bf16(acc[2 * g + 1], al, bh[2], bh[3]);
            }
        }
        if (c + 1 < NCH) {
            asm volatile("cp.async.wait_group 0;" ::: "memory");
            __syncthreads();
            do_convert((c + 1) * CHUNK);
            __syncthreads();
            if (c + 2 < NCH) issue_cp((c + 2) * CHUNK);
        }
    }

    // ---- epilogue: stage accs, coalesced write + fused 13-bit hist1 ----
    __syncthreads();
    float* stg = reinterpret_cast<float*>(smem);
#pragma unroll
    for (int ni = 0; ni < 8; ni++) {
        int row = wid * 16 + (lid >> 2);
        int col = ni * 8 + 2 * (lid & 3);
        *reinterpret_cast<float2*>(&stg[row * STGW + col]) =
            make_float2(acc[ni][0], acc[ni][1]);
        *reinterpret_cast<float2*>(&stg[(row + 8) * STGW + col]) =
            make_float2(acc[ni][2], acc[ni][3]);
    }
    __syncthreads();

    const float* nz = noise + (size_t)rowBase * NEXP;
    float* op = out + (size_t)rowBase * NEXP;
#pragma unroll
    for (int j = 0; j < 8; j++) {
        int l = tid + j * NTHR;
        int r = l >> 4, q = (l & 15) * 4;
        float4 nv = *reinterpret_cast<const float4*>(nz + r * NEXP + q);
        float4 bv = *reinterpret_cast<const float4*>(bias + q);
        float4 o;
        o.x = (stg[r * STGW + q + 0] + bv.x) + 0.1f * nv.x;
        o.y = (stg[r * STGW + q + 1] + bv.y) + 0.1f * nv.y;
        o.z = (stg[r * STGW + q + 2] + bv.z) + 0.1f * nv.z;
        o.w = (stg[r * STGW + q + 3] + bv.w) + 0.1f * nv.w;
        *reinterpret_cast<float4*>(op + r * NEXP + q) = o;
        atomicAdd(&g_hist1[((q + 0) << 13) | (f2o(o.x) >> 19)], 1u);
        atomicAdd(&g_hist1[((q + 1) << 13) | (f2o(o.y) >> 19)], 1u);
        atomicAdd(&g_hist1[((q + 2) << 13) | (f2o(o.z) >> 19)], 1u);
        atomicAdd(&g_hist1[((q + 3) << 13) | (f2o(o.w) >> 19)], 1u);
    }
}

// ---------------- launch idx 4: locate quantile buckets ----------------
__global__ void find_buckets() {
    const int e = blockIdx.x;
    const uint32_t* h = &g_hist1[e << 13];
    const int t = threadIdx.x, lane = t & 31, w = t >> 5;
    __shared__ uint32_t sh[NBINS];
    for (int i = t; i < NBINS; i += 256) sh[i] = h[i];
    __syncthreads();
    uint32_t bins[32];
    uint32_t s = 0;
#pragma unroll
    for (int j = 0; j < 32; j++) { bins[j] = sh[t * 32 + j]; s += bins[j]; }
    __shared__ uint32_t wsum[8], woff[8];
    uint32_t ps = warp_iscan(s, lane);
    if (lane == 31) wsum[w] = ps;
    __syncthreads();
    if (t == 0) {
        uint32_t r2 = 0;
        for (int i = 0; i < 8; i++) { woff[i] = r2; r2 += wsum[i]; }
    }
    __syncthreads();
    uint32_t base = woff[w] + ps - s;
    __shared__ uint32_t rbin[2], rrnk[2];
    for (int ri = 0; ri < 2; ri++) {
        uint32_t r = CRANK0 + (uint32_t)ri;
        if (base <= r && r < base + s) {
            uint32_t cum = base;
#pragma unroll
            for (int j = 0; j < 32; j++) {
                if (r < cum + bins[j]) { rbin[ri] = (uint32_t)(t * 32 + j); rrnk[ri] = r - cum; break; }
                cum += bins[j];
            }
        }
    }
    __syncthreads();
    if (t == 0) {
        g_bkt0[e] = rbin[0]; g_rnk0[e] = rrnk[0];
        g_bkt1[e] = rbin[1]; g_rnk1[e] = rrnk[1];
    }
}

// ---------------- launch idx 5: collect candidates ----------------
__global__ void collect_pass(const float4* __restrict__ lg, int n4) {
    __shared__ uint32_t b0s[NEXP], b1s[NEXP];
    if (threadIdx.x < NEXP) {
        b0s[threadIdx.x] = g_bkt0[threadIdx.x];
        b1s[threadIdx.x] = g_bkt1[threadIdx.x];
    }
    __syncthreads();
    for (int i = blockIdx.x * blockDim.x + threadIdx.x; i < n4;
         i += gridDim.x * blockDim.x) {
        float4 v = lg[i];
        int col = (i * 4) & 63;
        float vals[4] = {v.x, v.y, v.z, v.w};
#pragma unroll
        for (int j = 0; j < 4; j++) {
            uint32_t u = f2o(vals[j]);
            uint32_t hb = u >> 19;
            int c = col + j;
            if (hb == b0s[c]) {
                uint32_t pos = atomicAdd(&g_cnt[c], 1u);
                if (pos < CAP) g_cand[(c << 13) | pos] = u;
            }
            if (b1s[c] != b0s[c] && hb == b1s[c]) atomicMin(&g_minb1[c], u);
        }
    }
}

// ---------------- launch idx 6: exact order-stats from candidates ------------
__global__ void select_kernel() {
    const int e = blockIdx.x;
    const int tid = threadIdx.x, lane = tid & 31, w = tid >> 5;
    __shared__ uint32_t hist[4096];
    const uint32_t* cand = &g_cand[e << 13];
    int n = (int)g_cnt[e]; if (n > CAP) n = CAP;
    const uint32_t b0 = g_bkt0[e], b1 = g_bkt1[e];
    const int two = (b0 == b1) ? 1 : 0;
#pragma unroll
    for (int j = 0; j < 16; j++) hist[tid * 16 + j] = 0u;
    __syncthreads();
    for (int i = tid; i < n; i += 256) atomicAdd(&hist[(cand[i] >> 7) & 0xFFFu], 1u);
    __syncthreads();
    uint32_t loc[16];
    uint32_t s = 0;
#pragma unroll
    for (int j = 0; j < 16; j++) { loc[j] = hist[tid * 16 + j]; s += loc[j]; }
    __shared__ uint32_t wsum[8], woff[8];
    uint32_t ps = warp_iscan(s, lane);
    if (lane == 31) wsum[w] = ps;
    __syncthreads();
    if (tid == 0) {
        uint32_t r2 = 0;
        for (int i = 0; i < 8; i++) { woff[i] = r2; r2 += wsum[i]; }
    }
    __syncthreads();
    uint32_t base = woff[w] + ps - s;
    __shared__ uint32_t tb[2], bb[2];
    uint32_t ranks[2] = {g_rnk0[e], g_rnk1[e]};
    for (int ri = 0; ri <= two; ri++) {
        uint32_t r = ranks[ri];
        if (base <= r && r < base + s) {
            uint32_t cum = base;
#pragma unroll
            for (int j = 0; j < 16; j++) {
                if (r < cum + loc[j]) { tb[ri] = (uint32_t)(tid * 16 + j); bb[ri] = cum; break; }
                cum += loc[j];
            }
        }
    }
    __syncthreads();
    __shared__ uint32_t mbuf[2][64];
    __shared__ uint32_t mcnt[2];
    if (tid < 2) mcnt[tid] = 0u;
    __syncthreads();
    for (int i = tid; i < n; i += 256) {
        uint32_t u = cand[i];
        uint32_t bin = (u >> 7) & 0xFFFu;
        for (int ri = 0; ri <= two; ri++) {
            if (bin == tb[ri]) {
                uint32_t k = atomicAdd(&mcnt[ri], 1u);
                if (k < 64) mbuf[ri][k] = u;
            }
        }
    }
    __syncthreads();
    if (tid == 0) {
        uint32_t vals[2];
        for (int ri = 0; ri <= two; ri++) {
            int m = (int)mcnt[ri]; if (m > 64) m = 64;
            for (int i2 = 1; i2 < m; i2++) {
                uint32_t key = mbuf[ri][i2];
                int j2 = i2 - 1;
                while (j2 >= 0 && mbuf[ri][j2] > key) { mbuf[ri][j2 + 1] = mbuf[ri][j2]; j2--; }
                mbuf[ri][j2 + 1] = key;
            }
            vals[ri] = mbuf[ri][ranks[ri] - bb[ri]];
        }
        float s0 = o2f(vals[0]);
        float s1 = two ? o2f(vals[1]) : o2f(g_minb1[e]);
        g_tcol[e] = s0 + 0.25f * (s1 - s0);
    }
}

// ---------------- launch idx 7: row masks + softmax ----------------
__global__ __launch_bounds__(256) void row_kernel(float* __restrict__ lg) {
    __shared__ float tc[NEXP];
    const int tid = threadIdx.x;
    if (tid < NEXP) tc[tid] = g_tcol[tid];
    __syncthreads();
    const int lane = tid & 31;
    const int w = tid >> 5;
    const int row = blockIdx.x * 8 + w;

    float v0 = lg[row * NEXP + lane];
    float v1 = lg[row * NEXP + 32 + lane];
    float m0 = (v0 > tc[lane])      ? v0 : HIGH_NEG;
    float m1 = (v1 > tc[lane + 32]) ? v1 : HIGH_NEG;

    float a = fmaxf(m0, m1), b = fminf(m0, m1), c = -3.402823466e38f;
#pragma unroll
    for (int off = 16; off > 0; off >>= 1) {
        float a2 = __shfl_xor_sync(0xffffffffu, a, off);
        float b2 = __shfl_xor_sync(0xffffffffu, b, off);
        float c2 = __shfl_xor_sync(0xffffffffu, c, off);
        float o1, o2, o3;
        if (a >= a2) {
            o1 = a;
            if (b >= a2) { o2 = b;  o3 = fmaxf(c, a2); }
            else         { o2 = a2; o3 = fmaxf(b, b2); }
        } else {
            o1 = a2;
            if (b2 >= a) { o2 = b2; o3 = fmaxf(c2, a); }
            else         { o2 = a;  o3 = fmaxf(b, b2); }
        }
        a = o1; b = o2; c = o3;
    }
    float thr = c + 0.03125f * (b - c);
    float w0 = (m0 > thr) ? m0 : HIGH_NEG;
    float w1 = (m1 > thr) ? m1 : HIGH_NEG;
    float M = (a > thr) ? a : HIGH_NEG;

    float e0 = expf(w0 - M);
    float e1 = expf(w1 - M);
    float ssum = e0 + e1;
#pragma unroll
    for (int off = 16; off > 0; off >>= 1)
        ssum += __shfl_xor_sync(0xffffffffu, ssum, off);

    lg[row * NEXP + lane]      = e0 / ssum;
    lg[row * NEXP + 32 + lane] = e1 / ssum;
}

// ---------------- launch ----------------
extern "C" void kernel_launch(void* const* d_in, const int* in_sizes, int n_in,
                              void* d_out, int out_size) {
    const float *x = nullptr, *noise = nullptr, *W = nullptr, *bias = nullptr;
    for (int i = 0; i < n_in; i++) {
        switch (in_sizes[i]) {
            case NROWS * KDIM: x     = (const float*)d_in[i]; break;
            case NROWS * NEXP: noise = (const float*)d_in[i]; break;
            case NEXP * KDIM:  W     = (const float*)d_in[i]; break;
            case NEXP:         bias  = (const float*)d_in[i]; break;
            default: break;
        }
    }
    float* out = (float*)d_out;
    const int n4 = NROWS * NEXP / 4;

    cudaFuncSetAttribute(gemm_mma, cudaFuncAttributeMaxDynamicSharedMemorySize, SMEM_TOTAL);

    zero_hist1<<<NEXP * NBINS / 4 / 256, 256>>>();          // idx 0
    w_convert<<<NEXP * KDIM / 256, 256>>>(W);               // idx 1
    init_small<<<1, 64>>>();                                // idx 2
    gemm_mma<<<NROWS / BM, NTHR, SMEM_TOTAL>>>(x, bias, noise, out);  // idx 3 (profiled)
    find_buckets<<<NEXP, 256>>>();                          // idx 4
    collect_pass<<<4096, 256>>>((const float4*)out, n4);    // idx 5
    select_kernel<<<NEXP, 256>>>();                         // idx 6
    row_kernel<<<NROWS / 8, 256>>>(out);                    // idx 7
}

// round 8
// speedup vs baseline: 1.0897x; 1.0897x over previous
#include <cuda_runtime.h>
#include <cuda_bf16.h>
#include <cstdint>

#define NEXP 64
#define KDIM 1024
#define NROWS 131072
#define HIGH_NEG -100000.0f
#define CRANK0 98303u

// ---------------- scratch ----------------
#define NBINS 8192               // 13-bit level-1 histogram
#define CAP 8192                 // candidate capacity per expert
__device__ uint32_t g_hist1[NEXP * NBINS];
__device__ uint32_t g_cand[NEXP * CAP];
__device__ uint32_t g_cnt[NEXP];
__device__ uint32_t g_minb1[NEXP];
__device__ uint32_t g_bkt0[NEXP], g_rnk0[NEXP], g_bkt1[NEXP], g_rnk1[NEXP];
__device__ float    g_tcol[NEXP];
__device__ __nv_bfloat16 g_whi[NEXP * KDIM];
__device__ __nv_bfloat16 g_wlo[NEXP * KDIM];

// ---------------- helpers ----------------
__device__ __forceinline__ uint32_t f2o(float f) {
    uint32_t u = __float_as_uint(f);
    return u ^ ((u & 0x80000000u) ? 0xFFFFFFFFu : 0x80000000u);
}
__device__ __forceinline__ float o2f(uint32_t u) {
    u ^= ((u & 0x80000000u) ? 0x80000000u : 0xFFFFFFFFu);
    return __uint_as_float(u);
}
__device__ __forceinline__ uint32_t smem_u32(const void* p) {
    uint32_t a;
    asm("{ .reg .u64 t; cvta.to.shared.u64 t, %1; cvt.u32.u64 %0, t; }" : "=r"(a) : "l"(p));
    return a;
}
__device__ __forceinline__ void ldmx4(uint32_t* r, uint32_t addr) {
    asm volatile("ldmatrix.sync.aligned.m8n8.x4.shared.b16 {%0,%1,%2,%3}, [%4];"
                 : "=r"(r[0]), "=r"(r[1]), "=r"(r[2]), "=r"(r[3]) : "r"(addr));
}
__device__ __forceinline__ void mma_bf16(float* d, const uint32_t* a,
                                         uint32_t b0, uint32_t b1) {
    asm volatile(
        "mma.sync.aligned.m16n8k16.row.col.f32.bf16.bf16.f32 "
        "{%0,%1,%2,%3}, {%4,%5,%6,%7}, {%8,%9}, {%0,%1,%2,%3};"
        : "+f"(d[0]), "+f"(d[1]), "+f"(d[2]), "+f"(d[3])
        : "r"(a[0]), "r"(a[1]), "r"(a[2]), "r"(a[3]), "r"(b0), "r"(b1));
}
__device__ __forceinline__ void cpasync16(uint32_t dst, const void* src) {
    asm volatile("cp.async.cg.shared.global [%0], [%1], 16;"
                 :: "r"(dst), "l"(src) : "memory");
}
__device__ __forceinline__ uint32_t warp_iscan(uint32_t v, int lane) {
#pragma unroll
    for (int o = 1; o < 32; o <<= 1) {
        uint32_t t = __shfl_up_sync(0xffffffffu, v, o);
        if (lane >= o) v += t;
    }
    return v;
}

// ---------------- launch idx 0: zero hist1 ----------------
__global__ void zero_hist1() {
    uint4* a = reinterpret_cast<uint4*>(g_hist1);
    int i = blockIdx.x * blockDim.x + threadIdx.x;
    a[i] = make_uint4(0u, 0u, 0u, 0u);
}

// ---------------- launch idx 1: W -> bf16 hi/lo ----------------
__global__ void w_convert(const float* __restrict__ W) {
    int i = blockIdx.x * blockDim.x + threadIdx.x;
    float v = W[i];
    __nv_bfloat16 h = __float2bfloat16(v);
    g_whi[i] = h;
    g_wlo[i] = __float2bfloat16(v - __bfloat162float(h));
}

// ---------------- launch idx 2: small inits ----------------
__global__ void init_small() {
    if (threadIdx.x < NEXP) {
        g_cnt[threadIdx.x] = 0u;
        g_minb1[threadIdx.x] = 0xFFFFFFFFu;
    }
}

// ---------------- launch idx 3: cp.async-pipelined mma GEMM ------------------
#define BM 128
#define CHUNK 64
#define NCH (KDIM / CHUNK)
// smem layout (112 KB):
#define STAG(b) ((b) * 32768)          // 2 x 32KB fp32 staging ring
#define SM_A_HI 65536                  // 128 x 128B swizzled bf16
#define SM_A_LO 81920
#define SM_B_HI 98304                  // 64 x 128B swizzled bf16
#define SM_B_LO 106496
#define SMEM_TOTAL 114688
#define STG 68

__global__ __launch_bounds__(256, 2) void gemm_mma(
    const float* __restrict__ x, const float* __restrict__ bias,
    const float* __restrict__ noise, float* __restrict__ out)
{
    extern __shared__ char smem[];
    const uint32_t sb = smem_u32(smem);
    const int tid = threadIdx.x;
    const int wid = tid >> 5, lid = tid & 31;
    const int wm = wid >> 2, wn = wid & 3;     // warp grid 2 x 4
    const int rowBase = blockIdx.x * BM;
    const float* xr = x + (size_t)rowBase * KDIM;

    float acc[4][2][4];
#pragma unroll
    for (int mi = 0; mi < 4; mi++)
#pragma unroll
        for (int ni = 0; ni < 2; ni++)
#pragma unroll
            for (int j = 0; j < 4; j++) acc[mi][ni][j] = 0.0f;

    // ldmatrix A: row = wm*64 + mi*16 + (lid&15); (row&7) = (lid&7)
    const uint32_t amask = (uint32_t)((lid & 7) << 4);
    const uint32_t asel = (uint32_t)((lid >> 4) * 16);
    const uint32_t aBaseH = sb + SM_A_HI + (uint32_t)(wm * 64 + (lid & 15)) * 128;
    const uint32_t aBaseL = aBaseH + (SM_A_LO - SM_A_HI);
    // ldmatrix B: row = wn*16 + ((lid>>4)<<3) + (lid&7); (row&7) = (lid&7)
    const uint32_t bsel = (uint32_t)(((lid >> 3) & 1) * 16);
    const uint32_t bBaseH = sb + SM_B_HI +
        (uint32_t)(wn * 16 + ((lid >> 4) << 3) + (lid & 7)) * 128;
    const uint32_t bBaseL = bBaseH + (SM_B_LO - SM_B_HI);

    // ---- prologue: issue cp.async for chunks 0 and 1 ----
#pragma unroll
    for (int g = 0; g < 2; g++) {
#pragma unroll
        for (int i = 0; i < 8; i++) {
            int l = tid + i * 256;
            int r = l >> 4, q = l & 15;
            cpasync16(sb + STAG(g) + (uint32_t)(r * 256 + q * 16),
                      xr + (size_t)r * KDIM + g * CHUNK + q * 4);
        }
        asm volatile("cp.async.commit_group;" ::: "memory");
    }
    asm volatile("cp.async.wait_group 1;" ::: "memory");
    __syncthreads();

    for (int c = 0; c < NCH; c++) {
        const int buf = c & 1;
        const int kc = c * CHUNK;
        // ---- convert staging -> swizzled bf16 tiles ----
#pragma unroll
        for (int i = 0; i < 8; i++) {
            int l = tid + i * 256;
            int r = l >> 4, q = l & 15;
            float4 v = *reinterpret_cast<const float4*>(
                smem + STAG(buf) + r * 256 + q * 16);
            uint32_t h01, h23, l01, l23;
            asm("cvt.rn.bf16x2.f32 %0, %1, %2;" : "=r"(h01) : "f"(v.y), "f"(v.x));
            asm("cvt.rn.bf16x2.f32 %0, %1, %2;" : "=r"(h23) : "f"(v.w), "f"(v.z));
            float r0 = v.x - __uint_as_float(h01 << 16);
            float r1 = v.y - __uint_as_float(h01 & 0xFFFF0000u);
            float r2 = v.z - __uint_as_float(h23 << 16);
            float r3 = v.w - __uint_as_float(h23 & 0xFFFF0000u);
            asm("cvt.rn.bf16x2.f32 %0, %1, %2;" : "=r"(l01) : "f"(r1), "f"(r0));
            asm("cvt.rn.bf16x2.f32 %0, %1, %2;" : "=r"(l23) : "f"(r3), "f"(r2));
            uint32_t off = (uint32_t)(r * 128) +
                           (((uint32_t)(q * 8)) ^ ((uint32_t)((r & 7) << 4)));
            *reinterpret_cast<uint2*>(smem + SM_A_HI + off) = make_uint2(h01, h23);
            *reinterpret_cast<uint2*>(smem + SM_A_LO + off) = make_uint2(l01, l23);
        }
        {
            const uint4* wh = reinterpret_cast<const uint4*>(g_whi);
            const uint4* wl = reinterpret_cast<const uint4*>(g_wlo);
#pragma unroll
            for (int i = 0; i < 2; i++) {
                int l = tid + i * 256;
                int e = l >> 3, q = l & 7;
                uint32_t src = (uint32_t)(e * KDIM + kc) >> 3;
                uint32_t off = (uint32_t)(e * 128) +
                               (((uint32_t)(q * 16)) ^ ((uint32_t)((e & 7) << 4)));
                *reinterpret_cast<uint4*>(smem + SM_B_HI + off) = wh[src + q];
                *reinterpret_cast<uint4*>(smem + SM_B_LO + off) = wl[src + q];
            }
        }
        __syncthreads();

        // ---- issue cp.async for chunk c+2 into the buffer just consumed ----
        if (c + 2 < NCH) {
            const int kn = kc + 2 * CHUNK;
#pragma unroll
            for (int i = 0; i < 8; i++) {
                int l = tid + i * 256;
                int r = l >> 4, q = l & 15;
                cpasync16(sb + STAG(buf) + (uint32_t)(r * 256 + q * 16),
                          xr + (size_t)r * KDIM + kn + q * 4);
            }
            asm volatile("cp.async.commit_group;" ::: "memory");
        }

        // ---- mma over chunk: pass-major order (breaks RAW chains on acc) ----
#pragma unroll
        for (int kk = 0; kk < 4; kk++) {
            const uint32_t ca = (asel + (uint32_t)(kk * 32)) ^ amask;
            const uint32_t cb = (bsel + (uint32_t)(kk * 32)) ^ amask;
            uint32_t bh[4], bl[4];
            ldmx4(bh, bBaseH + cb);
            ldmx4(bl, bBaseL + cb);
            uint32_t ah[4][4], al[4][4];
#pragma unroll
            for (int mi = 0; mi < 4; mi++) {
                ldmx4(ah[mi], aBaseH + (uint32_t)(mi * 2048) + ca);
                ldmx4(al[mi], aBaseL + (uint32_t)(mi * 2048) + ca);
            }
            // pass 1: hi*hi  (8 independent accumulators)
#pragma unroll
            for (int mi = 0; mi < 4; mi++)
#pragma unroll
                for (int ni = 0; ni < 2; ni++)
                    mma_bf16(acc[mi][ni], ah[mi], bh[ni * 2], bh[ni * 2 + 1]);
            // pass 2: hi*lo
#pragma unroll
            for (int mi = 0; mi < 4; mi++)
#pragma unroll
                for (int ni = 0; ni < 2; ni++)
                    mma_bf16(acc[mi][ni], ah[mi], bl[ni * 2], bl[ni * 2 + 1]);
            // pass 3: lo*hi
#pragma unroll
            for (int mi = 0; mi < 4; mi++)
#pragma unroll
                for (int ni = 0; ni < 2; ni++)
                    mma_bf16(acc[mi][ni], al[mi], bh[ni * 2], bh[ni * 2 + 1]);
        }
        // ---- drain: next convert needs chunk c+1 complete ----
        if (c + 1 < NCH) {
            if (c + 2 < NCH) {
                asm volatile("cp.async.wait_group 1;" ::: "memory");
            } else {
                asm volatile("cp.async.wait_group 0;" ::: "memory");
            }
        }
        __syncthreads();
    }

    // ---- epilogue: stage accs (reuse staging area), coalesced write + hist1 ----
    float* stg = reinterpret_cast<float*>(smem);
#pragma unroll
    for (int mi = 0; mi < 4; mi++) {
        int row = wm * 64 + mi * 16 + (lid >> 2);
        int col = wn * 16 + 2 * (lid & 3);
#pragma unroll
        for (int ni = 0; ni < 2; ni++) {
            int cc = col + ni * 8;
            *reinterpret_cast<float2*>(&stg[row * STG + cc]) =
                make_float2(acc[mi][ni][0], acc[mi][ni][1]);
            *reinterpret_cast<float2*>(&stg[(row + 8) * STG + cc]) =
                make_float2(acc[mi][ni][2], acc[mi][ni][3]);
        }
    }
    __syncthreads();

    const float* nz = noise + (size_t)rowBase * NEXP;
    float* op = out + (size_t)rowBase * NEXP;
#pragma unroll
    for (int j = 0; j < 8; j++) {
        int l = tid + j * 256;
        int r = l >> 4, q = (l & 15) * 4;
        float4 nv = *reinterpret_cast<const float4*>(nz + r * NEXP + q);
        float4 bv = *reinterpret_cast<const float4*>(bias + q);
        float4 o;
        o.x = (stg[r * STG + q + 0] + bv.x) + 0.1f * nv.x;
        o.y = (stg[r * STG + q + 1] + bv.y) + 0.1f * nv.y;
        o.z = (stg[r * STG + q + 2] + bv.z) + 0.1f * nv.z;
        o.w = (stg[r * STG + q + 3] + bv.w) + 0.1f * nv.w;
        *reinterpret_cast<float4*>(op + r * NEXP + q) = o;
        atomicAdd(&g_hist1[((q + 0) << 13) | (f2o(o.x) >> 19)], 1u);
        atomicAdd(&g_hist1[((q + 1) << 13) | (f2o(o.y) >> 19)], 1u);
        atomicAdd(&g_hist1[((q + 2) << 13) | (f2o(o.z) >> 19)], 1u);
        atomicAdd(&g_hist1[((q + 3) << 13) | (f2o(o.w) >> 19)], 1u);
    }
}

// ---------------- launch idx 4: locate quantile buckets ----------------
__global__ void find_buckets() {
    const int e = blockIdx.x;
    const uint32_t* h = &g_hist1[e << 13];
    const int t = threadIdx.x, lane = t & 31, w = t >> 5;
    __shared__ uint32_t sh[NBINS];
    for (int i = t; i < NBINS; i += 256) sh[i] = h[i];
    __syncthreads();
    uint32_t bins[32];
    uint32_t s = 0;
#pragma unroll
    for (int j = 0; j < 32; j++) { bins[j] = sh[t * 32 + j]; s += bins[j]; }
    __shared__ uint32_t wsum[8], woff[8];
    uint32_t ps = warp_iscan(s, lane);
    if (lane == 31) wsum[w] = ps;
    __syncthreads();
    if (t == 0) {
        uint32_t r2 = 0;
        for (int i = 0; i < 8; i++) { woff[i] = r2; r2 += wsum[i]; }
    }
    __syncthreads();
    uint32_t base = woff[w] + ps - s;
    __shared__ uint32_t rbin[2], rrnk[2];
    for (int ri = 0; ri < 2; ri++) {
        uint32_t r = CRANK0 + (uint32_t)ri;
        if (base <= r && r < base + s) {
            uint32_t cum = base;
#pragma unroll
            for (int j = 0; j < 32; j++) {
                if (r < cum + bins[j]) { rbin[ri] = (uint32_t)(t * 32 + j); rrnk[ri] = r - cum; break; }
                cum += bins[j];
            }
        }
    }
    __syncthreads();
    if (t == 0) {
        g_bkt0[e] = rbin[0]; g_rnk0[e] = rrnk[0];
        g_bkt1[e] = rbin[1]; g_rnk1[e] = rrnk[1];
    }
}

// ---------------- launch idx 5: collect candidates ----------------
__global__ void collect_pass(const float4* __restrict__ lg, int n4) {
    __shared__ uint32_t b0s[NEXP], b1s[NEXP];
    if (threadIdx.x < NEXP) {
        b0s[threadIdx.x] = g_bkt0[threadIdx.x];
        b1s[threadIdx.x] = g_bkt1[threadIdx.x];
    }
    __syncthreads();
    for (int i = blockIdx.x * blockDim.x + threadIdx.x; i < n4;
         i += gridDim.x * blockDim.x) {
        float4 v = lg[i];
        int col = (i * 4) & 63;
        float vals[4] = {v.x, v.y, v.z, v.w};
#pragma unroll
        for (int j = 0; j < 4; j++) {
            uint32_t u = f2o(vals[j]);
            uint32_t hb = u >> 19;
            int c = col + j;
            if (hb == b0s[c]) {
                uint32_t pos = atomicAdd(&g_cnt[c], 1u);
                if (pos < CAP) g_cand[(c << 13) | pos] = u;
            }
            if (b1s[c] != b0s[c] && hb == b1s[c]) atomicMin(&g_minb1[c], u);
        }
    }
}

// ---------------- launch idx 6: exact order-stats from candidates ------------
__global__ void select_kernel() {
    const int e = blockIdx.x;
    const int tid = threadIdx.x, lane = tid & 31, w = tid >> 5;
    __shared__ uint32_t hist[4096];
    const uint32_t* cand = &g_cand[e << 13];
    int n = (int)g_cnt[e]; if (n > CAP) n = CAP;
    const uint32_t b0 = g_bkt0[e], b1 = g_bkt1[e];
    const int two = (b0 == b1) ? 1 : 0;
#pragma unroll
    for (int j = 0; j < 16; j++) hist[tid * 16 + j] = 0u;
    __syncthreads();
    for (int i = tid; i < n; i += 256) atomicAdd(&hist[(cand[i] >> 7) & 0xFFFu], 1u);
    __syncthreads();
    uint32_t loc[16];
    uint32_t s = 0;
#pragma unroll
    for (int j = 0; j < 16; j++) { loc[j] = hist[tid * 16 + j]; s += loc[j]; }
    __shared__ uint32_t wsum[8], woff[8];
    uint32_t ps = warp_iscan(s, lane);
    if (lane == 31) wsum[w] = ps;
    __syncthreads();
    if (tid == 0) {
        uint32_t r2 = 0;
        for (int i = 0; i < 8; i++) { woff[i] = r2; r2 += wsum[i]; }
    }
    __syncthreads();
    uint32_t base = woff[w] + ps - s;
    __shared__ uint32_t tb[2], bb[2];
    uint32_t ranks[2] = {g_rnk0[e], g_rnk1[e]};
    for (int ri = 0; ri <= two; ri++) {
        uint32_t r = ranks[ri];
        if (base <= r && r < base + s) {
            uint32_t cum = base;
#pragma unroll
            for (int j = 0; j < 16; j++) {
                if (r < cum + loc[j]) { tb[ri] = (uint32_t)(tid * 16 + j); bb[ri] = cum; break; }
                cum += loc[j];
            }
        }
    }
    __syncthreads();
    __shared__ uint32_t mbuf[2][64];
    __shared__ uint32_t mcnt[2];
    if (tid < 2) mcnt[tid] = 0u;
    __syncthreads();
    for (int i = tid; i < n; i += 256) {
        uint32_t u = cand[i];
        uint32_t bin = (u >> 7) & 0xFFFu;
        for (int ri = 0; ri <= two; ri++) {
            if (bin == tb[ri]) {
                uint32_t k = atomicAdd(&mcnt[ri], 1u);
                if (k < 64) mbuf[ri][k] = u;
            }
        }
    }
    __syncthreads();
    if (tid == 0) {
        uint32_t vals[2];
        for (int ri = 0; ri <= two; ri++) {
            int m = (int)mcnt[ri]; if (m > 64) m = 64;
            for (int i2 = 1; i2 < m; i2++) {
                uint32_t key = mbuf[ri][i2];
                int j2 = i2 - 1;
                while (j2 >= 0 && mbuf[ri][j2] > key) { mbuf[ri][j2 + 1] = mbuf[ri][j2]; j2--; }
                mbuf[ri][j2 + 1] = key;
            }
            vals[ri] = mbuf[ri][ranks[ri] - bb[ri]];
        }
        float s0 = o2f(vals[0]);
        float s1 = two ? o2f(vals[1]) : o2f(g_minb1[e]);
        g_tcol[e] = s0 + 0.25f * (s1 - s0);
    }
}

// ---------------- launch idx 7: row masks + softmax ----------------
__global__ __launch_bounds__(256) void row_kernel(float* __restrict__ lg) {
    __shared__ float tc[NEXP];
    const int tid = threadIdx.x;
    if (tid < NEXP) tc[tid] = g_tcol[tid];
    __syncthreads();
    const int lane = tid & 31;
    const int w = tid >> 5;
    const int row = blockIdx.x * 8 + w;

    float v0 = lg[row * NEXP + lane];
    float v1 = lg[row * NEXP + 32 + lane];
    float m0 = (v0 > tc[lane])      ? v0 : HIGH_NEG;
    float m1 = (v1 > tc[lane + 32]) ? v1 : HIGH_NEG;

    float a = fmaxf(m0, m1), b = fminf(m0, m1), c = -3.402823466e38f;
#pragma unroll
    for (int off = 16; off > 0; off >>= 1) {
        float a2 = __shfl_xor_sync(0xffffffffu, a, off);
        float b2 = __shfl_xor_sync(0xffffffffu, b, off);
        float c2 = __shfl_xor_sync(0xffffffffu, c, off);
        float o1, o2, o3;
        if (a >= a2) {
            o1 = a;
            if (b >= a2) { o2 = b;  o3 = fmaxf(c, a2); }
            else         { o2 = a2; o3 = fmaxf(b, b2); }
        } else {
            o1 = a2;
            if (b2 >= a) { o2 = b2; o3 = fmaxf(c2, a); }
            else         { o2 = a;  o3 = fmaxf(b, b2); }
        }
        a = o1; b = o2; c = o3;
    }
    float thr = c + 0.03125f * (b - c);
    float w0 = (m0 > thr) ? m0 : HIGH_NEG;
    float w1 = (m1 > thr) ? m1 : HIGH_NEG;
    float M = (a > thr) ? a : HIGH_NEG;

    float e0 = expf(w0 - M);
    float e1 = expf(w1 - M);
    float ssum = e0 + e1;
#pragma unroll
    for (int off = 16; off > 0; off >>= 1)
        ssum += __shfl_xor_sync(0xffffffffu, ssum, off);

    lg[row * NEXP + lane]      = e0 / ssum;
    lg[row * NEXP + 32 + lane] = e1 / ssum;
}

// ---------------- launch ----------------
extern "C" void kernel_launch(void* const* d_in, const int* in_sizes, int n_in,
                              void* d_out, int out_size) {
    const float *x = nullptr, *noise = nullptr, *W = nullptr, *bias = nullptr;
    for (int i = 0; i < n_in; i++) {
        switch (in_sizes[i]) {
            case NROWS * KDIM: x     = (const float*)d_in[i]; break;
            case NROWS * NEXP: noise = (const float*)d_in[i]; break;
            case NEXP * KDIM:  W     = (const float*)d_in[i]; break;
            case NEXP:         bias  = (const float*)d_in[i]; break;
            default: break;
        }
    }
    float* out = (float*)d_out;
    const int n4 = NROWS * NEXP / 4;

    cudaFuncSetAttribute(gemm_mma, cudaFuncAttributeMaxDynamicSharedMemorySize, SMEM_TOTAL);

    zero_hist1<<<NEXP * NBINS / 4 / 256, 256>>>();          // idx 0
    w_convert<<<NEXP * KDIM / 256, 256>>>(W);               // idx 1
    init_small<<<1, 64>>>();                                // idx 2
    gemm_mma<<<NROWS / BM, 256, SMEM_TOTAL>>>(x, bias, noise, out);  // idx 3 (profiled)
    find_buckets<<<NEXP, 256>>>();                          // idx 4
    collect_pass<<<4096, 256>>>((const float4*)out, n4);    // idx 5
    select_kernel<<<NEXP, 256>>>();                         // idx 6
    row_kernel<<<NROWS / 8, 256>>>(out);                    // idx 7
}

// round 9
// speedup vs baseline: 1.1726x; 1.0760x over previous
#include <cuda_runtime.h>
#include <cuda_bf16.h>
#include <cstdint>

#define NEXP 64
#define KDIM 1024
#define NROWS 131072
#define HIGH_NEG -100000.0f
#define CRANK0 98303u

// ---------------- scratch ----------------
#define NBINS 8192
#define CAP 8192
__device__ uint32_t g_hist1[NEXP * NBINS];
__device__ uint32_t g_cand[NEXP * CAP];
__device__ uint32_t g_cnt[NEXP];
__device__ uint32_t g_minb1[NEXP];
__device__ uint32_t g_bkt0[NEXP], g_rnk0[NEXP], g_bkt1[NEXP], g_rnk1[NEXP];
__device__ float    g_tcol[NEXP];
__device__ __nv_bfloat16 g_whi[NEXP * KDIM];
__device__ __nv_bfloat16 g_wlo[NEXP * KDIM];

// ---------------- helpers ----------------
__device__ __forceinline__ uint32_t f2o(float f) {
    uint32_t u = __float_as_uint(f);
    return u ^ ((u & 0x80000000u) ? 0xFFFFFFFFu : 0x80000000u);
}
__device__ __forceinline__ float o2f(uint32_t u) {
    u ^= ((u & 0x80000000u) ? 0x80000000u : 0xFFFFFFFFu);
    return __uint_as_float(u);
}
__device__ __forceinline__ uint32_t smem_u32(const void* p) {
    uint32_t a;
    asm("{ .reg .u64 t; cvta.to.shared.u64 t, %1; cvt.u32.u64 %0, t; }" : "=r"(a) : "l"(p));
    return a;
}
__device__ __forceinline__ void ldmx4(uint32_t* r, uint32_t addr) {
    asm volatile("ldmatrix.sync.aligned.m8n8.x4.shared.b16 {%0,%1,%2,%3}, [%4];"
                 : "=r"(r[0]), "=r"(r[1]), "=r"(r[2]), "=r"(r[3]) : "r"(addr));
}
__device__ __forceinline__ void mma_bf16(float* d, const uint32_t* a,
                                         uint32_t b0, uint32_t b1) {
    asm volatile(
        "mma.sync.aligned.m16n8k16.row.col.f32.bf16.bf16.f32 "
        "{%0,%1,%2,%3}, {%4,%5,%6,%7}, {%8,%9}, {%0,%1,%2,%3};"
        : "+f"(d[0]), "+f"(d[1]), "+f"(d[2]), "+f"(d[3])
        : "r"(a[0]), "r"(a[1]), "r"(a[2]), "r"(a[3]), "r"(b0), "r"(b1));
}
__device__ __forceinline__ void cpasync16(uint32_t dst, const void* src) {
    asm volatile("cp.async.cg.shared.global [%0], [%1], 16;"
                 :: "r"(dst), "l"(src) : "memory");
}
__device__ __forceinline__ uint32_t warp_iscan(uint32_t v, int lane) {
#pragma unroll
    for (int o = 1; o < 32; o <<= 1) {
        uint32_t t = __shfl_up_sync(0xffffffffu, v, o);
        if (lane >= o) v += t;
    }
    return v;
}

// ---------------- launch idx 0: zero hist1 ----------------
__global__ void zero_hist1() {
    uint4* a = reinterpret_cast<uint4*>(g_hist1);
    int i = blockIdx.x * blockDim.x + threadIdx.x;
    a[i] = make_uint4(0u, 0u, 0u, 0u);
}

// ---------------- launch idx 1: W -> bf16 hi/lo ----------------
__global__ void w_convert(const float* __restrict__ W) {
    int i = blockIdx.x * blockDim.x + threadIdx.x;
    float v = W[i];
    __nv_bfloat16 h = __float2bfloat16(v);
    g_whi[i] = h;
    g_wlo[i] = __float2bfloat16(v - __bfloat162float(h));
}

// ---------------- launch idx 2: small inits ----------------
__global__ void init_small() {
    if (threadIdx.x < NEXP) {
        g_cnt[threadIdx.x] = 0u;
        g_minb1[threadIdx.x] = 0xFFFFFFFFu;
    }
}

// ---------------- launch idx 3: direct-fragment mma GEMM ---------------------
// A stays fp32 in swizzled staging; fragments loaded as float2 (LDS.64) in mma
// layout, converted to hi/lo bf16 in registers. B staged via cp.async (hi/lo
// bf16, SW-swizzled) and loaded with ldmatrix. One syncthreads per chunk.
#define BM 128
#define CHUNK 64
#define NCH (KDIM / CHUNK)
// smem (96 KB): A fp32 staging 2 x 32KB; B tiles 2 x 16KB (hi 8KB + lo 8KB)
#define STAGA(b) ((b) * 32768)
#define SMB(b) (65536 + (b) * 16384)
#define SMEM_TOTAL 98304
#define STG 68

__global__ __launch_bounds__(256, 2) void gemm_mma(
    const float* __restrict__ x, const float* __restrict__ bias,
    const float* __restrict__ noise, float* __restrict__ out)
{
    extern __shared__ char smem[];
    const uint32_t sb = smem_u32(smem);
    const int tid = threadIdx.x;
    const int wid = tid >> 5, lid = tid & 31;
    const int wm = wid >> 1, wn = wid & 1;     // warp grid 4 x 2
    const int rowBase = blockIdx.x * BM;
    const float* xr = x + (size_t)rowBase * KDIM;

    float acc[2][4][4];                         // [mi][ni][4]
#pragma unroll
    for (int mi = 0; mi < 2; mi++)
#pragma unroll
        for (int ni = 0; ni < 4; ni++)
#pragma unroll
            for (int j = 0; j < 4; j++) acc[mi][ni][j] = 0.0f;

    // A fragment addressing: row R = wm*32 + mi*16 + (lid>>2) (+8 for upper),
    // colbyte = kk*64 + half*32 + (lid&3)*8, swizzled by ((R&3)<<5) (R&3 == (lid>>2)&3)
    const uint32_t swA = ((uint32_t)((lid >> 2) & 3)) << 5;
    const uint32_t aCol = (uint32_t)((lid & 3) * 8);
    const uint32_t rA = (uint32_t)(wm * 32 + (lid >> 2));
    // B ldmatrix addressing: expert row e = wn*32 + g*16 + ((lid>>4)<<3) + (lid&7)
    const uint32_t bmask = (uint32_t)((lid & 7) << 4);
    const uint32_t bsel = (uint32_t)(((lid >> 3) & 1) * 16);
    const uint32_t bRow0 = (uint32_t)(wn * 32 + ((lid >> 4) << 3) + (lid & 7));

    // cp.async issue helpers (A: 8x16B/thread; B: 2x(hi+lo)x16B/thread)
    auto issue_chunk = [&](int kc, int bufsel) {
#pragma unroll
        for (int i = 0; i < 8; i++) {
            int l = tid + i * 256;
            int r = l >> 4, q = l & 15;
            uint32_t dst = sb + STAGA(bufsel) + (uint32_t)(r * 256) +
                           (((uint32_t)(q * 16)) ^ (((uint32_t)(r & 3)) << 5));
            cpasync16(dst, xr + (size_t)r * KDIM + kc + q * 4);
        }
        const char* whp = reinterpret_cast<const char*>(g_whi);
        const char* wlp = reinterpret_cast<const char*>(g_wlo);
#pragma unroll
        for (int i = 0; i < 2; i++) {
            int l = tid + i * 256;
            int e = l >> 3, q = l & 7;
            uint32_t off = (uint32_t)(e * 128) +
                           (((uint32_t)(q * 16)) ^ ((uint32_t)((e & 7) << 4)));
            size_t src = (size_t)(e * KDIM + kc) * 2 + q * 16;
            cpasync16(sb + SMB(bufsel) + off, whp + src);
            cpasync16(sb + SMB(bufsel) + 8192 + off, wlp + src);
        }
        asm volatile("cp.async.commit_group;" ::: "memory");
    };

    // ---- prologue: chunk 0 ----
    issue_chunk(0, 0);
    asm volatile("cp.async.wait_group 0;" ::: "memory");
    __syncthreads();

    for (int c = 0; c < NCH; c++) {
        const int buf = c & 1;
        if (c + 1 < NCH) issue_chunk((c + 1) * CHUNK, buf ^ 1);

        const uint32_t aBase = sb + STAGA(buf);
        const uint32_t bBase = sb + SMB(buf);
#pragma unroll
        for (int kk = 0; kk < 4; kk++) {
            // ---- load fp32 A fragments + convert to hi/lo in regs ----
            uint32_t ah[2][4], al[2][4];
#pragma unroll
            for (int mi = 0; mi < 2; mi++) {
                const uint32_t R = rA + (uint32_t)(mi * 16);
                const uint32_t cb0 = ((uint32_t)(kk * 64) + aCol) ^ swA;
                const uint32_t cb1 = ((uint32_t)(kk * 64 + 32) + aCol) ^ swA;
                float2 f0 = *reinterpret_cast<const float2*>(smem + (aBase - sb) + R * 256 + cb0);
                float2 f1 = *reinterpret_cast<const float2*>(smem + (aBase - sb) + (R + 8) * 256 + cb0);
                float2 f2 = *reinterpret_cast<const float2*>(smem + (aBase - sb) + R * 256 + cb1);
                float2 f3 = *reinterpret_cast<const float2*>(smem + (aBase - sb) + (R + 8) * 256 + cb1);
                float2 fs[4] = {f0, f1, f2, f3};
#pragma unroll
                for (int j = 0; j < 4; j++) {
                    uint32_t h;
                    asm("cvt.rn.bf16x2.f32 %0, %1, %2;" : "=r"(h) : "f"(fs[j].y), "f"(fs[j].x));
                    float r0 = fs[j].x - __uint_as_float(h << 16);
                    float r1 = fs[j].y - __uint_as_float(h & 0xFFFF0000u);
                    uint32_t lo;
                    asm("cvt.rn.bf16x2.f32 %0, %1, %2;" : "=r"(lo) : "f"(r1), "f"(r0));
                    ah[mi][j] = h;
                    al[mi][j] = lo;
                }
            }
            // ---- B fragments (hi/lo, 2 groups of 16 experts) ----
            uint32_t bh[8], bl[8];
            const uint32_t cbB = (bsel + (uint32_t)(kk * 32)) ^ bmask;
            ldmx4(bh,     bBase + bRow0 * 128 + cbB);
            ldmx4(bh + 4, bBase + (bRow0 + 16) * 128 + cbB);
            ldmx4(bl,     bBase + 8192 + bRow0 * 128 + cbB);
            ldmx4(bl + 4, bBase + 8192 + (bRow0 + 16) * 128 + cbB);

            // ---- 3 passes, pass-major (per-acc order: hh, hl, lh) ----
#pragma unroll
            for (int mi = 0; mi < 2; mi++)
#pragma unroll
                for (int ni = 0; ni < 4; ni++) {
                    int g = (ni >> 1) * 4 + (ni & 1) * 2;
                    mma_bf16(acc[mi][ni], ah[mi], bh[g], bh[g + 1]);
                }
#pragma unroll
            for (int mi = 0; mi < 2; mi++)
#pragma unroll
                for (int ni = 0; ni < 4; ni++) {
                    int g = (ni >> 1) * 4 + (ni & 1) * 2;
                    mma_bf16(acc[mi][ni], ah[mi], bl[g], bl[g + 1]);
                }
#pragma unroll
            for (int mi = 0; mi < 2; mi++)
#pragma unroll
                for (int ni = 0; ni < 4; ni++) {
                    int g = (ni >> 1) * 4 + (ni & 1) * 2;
                    mma_bf16(acc[mi][ni], al[mi], bh[g], bh[g + 1]);
                }
        }
        if (c + 1 < NCH) asm volatile("cp.async.wait_group 0;" ::: "memory");
        __syncthreads();
    }

    // ---- epilogue: stage accs (reuse A staging), coalesced write + hist1 ----
    float* stg = reinterpret_cast<float*>(smem);
#pragma unroll
    for (int mi = 0; mi < 2; mi++) {
        int row = wm * 32 + mi * 16 + (lid >> 2);
#pragma unroll
        for (int ni = 0; ni < 4; ni++) {
            int col = wn * 32 + ni * 8 + 2 * (lid & 3);
            *reinterpret_cast<float2*>(&stg[row * STG + col]) =
                make_float2(acc[mi][ni][0], acc[mi][ni][1]);
            *reinterpret_cast<float2*>(&stg[(row + 8) * STG + col]) =
                make_float2(acc[mi][ni][2], acc[mi][ni][3]);
        }
    }
    __syncthreads();

    const float* nz = noise + (size_t)rowBase * NEXP;
    float* op = out + (size_t)rowBase * NEXP;
#pragma unroll
    for (int j = 0; j < 8; j++) {
        int l = tid + j * 256;
        int r = l >> 4, q = (l & 15) * 4;
        float4 nv = *reinterpret_cast<const float4*>(nz + r * NEXP + q);
        float4 bv = *reinterpret_cast<const float4*>(bias + q);
        float4 o;
        o.x = (stg[r * STG + q + 0] + bv.x) + 0.1f * nv.x;
        o.y = (stg[r * STG + q + 1] + bv.y) + 0.1f * nv.y;
        o.z = (stg[r * STG + q + 2] + bv.z) + 0.1f * nv.z;
        o.w = (stg[r * STG + q + 3] + bv.w) + 0.1f * nv.w;
        *reinterpret_cast<float4*>(op + r * NEXP + q) = o;
        atomicAdd(&g_hist1[((q + 0) << 13) | (f2o(o.x) >> 19)], 1u);
        atomicAdd(&g_hist1[((q + 1) << 13) | (f2o(o.y) >> 19)], 1u);
        atomicAdd(&g_hist1[((q + 2) << 13) | (f2o(o.z) >> 19)], 1u);
        atomicAdd(&g_hist1[((q + 3) << 13) | (f2o(o.w) >> 19)], 1u);
    }
}

// ---------------- launch idx 4: locate quantile buckets ----------------
__global__ void find_buckets() {
    const int e = blockIdx.x;
    const uint32_t* h = &g_hist1[e << 13];
    const int t = threadIdx.x, lane = t & 31, w = t >> 5;
    __shared__ uint32_t sh[NBINS];
    for (int i = t; i < NBINS; i += 256) sh[i] = h[i];
    __syncthreads();
    uint32_t bins[32];
    uint32_t s = 0;
#pragma unroll
    for (int j = 0; j < 32; j++) { bins[j] = sh[t * 32 + j]; s += bins[j]; }
    __shared__ uint32_t wsum[8], woff[8];
    uint32_t ps = warp_iscan(s, lane);
    if (lane == 31) wsum[w] = ps;
    __syncthreads();
    if (t == 0) {
        uint32_t r2 = 0;
        for (int i = 0; i < 8; i++) { woff[i] = r2; r2 += wsum[i]; }
    }
    __syncthreads();
    uint32_t base = woff[w] + ps - s;
    __shared__ uint32_t rbin[2], rrnk[2];
    for (int ri = 0; ri < 2; ri++) {
        uint32_t r = CRANK0 + (uint32_t)ri;
        if (base <= r && r < base + s) {
            uint32_t cum = base;
#pragma unroll
            for (int j = 0; j < 32; j++) {
                if (r < cum + bins[j]) { rbin[ri] = (uint32_t)(t * 32 + j); rrnk[ri] = r - cum; break; }
                cum += bins[j];
            }
        }
    }
    __syncthreads();
    if (t == 0) {
        g_bkt0[e] = rbin[0]; g_rnk0[e] = rrnk[0];
        g_bkt1[e] = rbin[1]; g_rnk1[e] = rrnk[1];
    }
}

// ---------------- launch idx 5: collect candidates ----------------
__global__ void collect_pass(const float4* __restrict__ lg, int n4) {
    __shared__ uint32_t b0s[NEXP], b1s[NEXP];
    if (threadIdx.x < NEXP) {
        b0s[threadIdx.x] = g_bkt0[threadIdx.x];
        b1s[threadIdx.x] = g_bkt1[threadIdx.x];
    }
    __syncthreads();
    for (int i = blockIdx.x * blockDim.x + threadIdx.x; i < n4;
         i += gridDim.x * blockDim.x) {
        float4 v = lg[i];
        int col = (i * 4) & 63;
        float vals[4] = {v.x, v.y, v.z, v.w};
#pragma unroll
        for (int j = 0; j < 4; j++) {
            uint32_t u = f2o(vals[j]);
            uint32_t hb = u >> 19;
            int c = col + j;
            if (hb == b0s[c]) {
                uint32_t pos = atomicAdd(&g_cnt[c], 1u);
                if (pos < CAP) g_cand[(c << 13) | pos] = u;
            }
            if (b1s[c] != b0s[c] && hb == b1s[c]) atomicMin(&g_minb1[c], u);
        }
    }
}

// ---------------- launch idx 6: exact order-stats from candidates ------------
__global__ void select_kernel() {
    const int e = blockIdx.x;
    const int tid = threadIdx.x, lane = tid & 31, w = tid >> 5;
    __shared__ uint32_t hist[4096];
    const uint32_t* cand = &g_cand[e << 13];
    int n = (int)g_cnt[e]; if (n > CAP) n = CAP;
    const uint32_t b0 = g_bkt0[e], b1 = g_bkt1[e];
    const int two = (b0 == b1) ? 1 : 0;
#pragma unroll
    for (int j = 0; j < 16; j++) hist[tid * 16 + j] = 0u;
    __syncthreads();
    for (int i = tid; i < n; i += 256) atomicAdd(&hist[(cand[i] >> 7) & 0xFFFu], 1u);
    __syncthreads();
    uint32_t loc[16];
    uint32_t s = 0;
#pragma unroll
    for (int j = 0; j < 16; j++) { loc[j] = hist[tid * 16 + j]; s += loc[j]; }
    __shared__ uint32_t wsum[8], woff[8];
    uint32_t ps = warp_iscan(s, lane);
    if (lane == 31) wsum[w] = ps;
    __syncthreads();
    if (tid == 0) {
        uint32_t r2 = 0;
        for (int i = 0; i < 8; i++) { woff[i] = r2; r2 += wsum[i]; }
    }
    __syncthreads();
    uint32_t base = woff[w] + ps - s;
    __shared__ uint32_t tb[2], bb[2];
    uint32_t ranks[2] = {g_rnk0[e], g_rnk1[e]};
    for (int ri = 0; ri <= two; ri++) {
        uint32_t r = ranks[ri];
        if (base <= r && r < base + s) {
            uint32_t cum = base;
#pragma unroll
            for (int j = 0; j < 16; j++) {
                if (r < cum + loc[j]) { tb[ri] = (uint32_t)(tid * 16 + j); bb[ri] = cum; break; }
                cum += loc[j];
            }
        }
    }
    __syncthreads();
    __shared__ uint32_t mbuf[2][64];
    __shared__ uint32_t mcnt[2];
    if (tid < 2) mcnt[tid] = 0u;
    __syncthreads();
    for (int i = tid; i < n; i += 256) {
        uint32_t u = cand[i];
        uint32_t bin = (u >> 7) & 0xFFFu;
        for (int ri = 0; ri <= two; ri++) {
            if (bin == tb[ri]) {
                uint32_t k = atomicAdd(&mcnt[ri], 1u);
                if (k < 64) mbuf[ri][k] = u;
            }
        }
    }
    __syncthreads();
    if (tid == 0) {
        uint32_t vals[2];
        for (int ri = 0; ri <= two; ri++) {
            int m = (int)mcnt[ri]; if (m > 64) m = 64;
            for (int i2 = 1; i2 < m; i2++) {
                uint32_t key = mbuf[ri][i2];
                int j2 = i2 - 1;
                while (j2 >= 0 && mbuf[ri][j2] > key) { mbuf[ri][j2 + 1] = mbuf[ri][j2]; j2--; }
                mbuf[ri][j2 + 1] = key;
            }
            vals[ri] = mbuf[ri][ranks[ri] - bb[ri]];
        }
        float s0 = o2f(vals[0]);
        float s1 = two ? o2f(vals[1]) : o2f(g_minb1[e]);
        g_tcol[e] = s0 + 0.25f * (s1 - s0);
    }
}

// ---------------- launch idx 7: row masks + softmax ----------------
__global__ __launch_bounds__(256) void row_kernel(float* __restrict__ lg) {
    __shared__ float tc[NEXP];
    const int tid = threadIdx.x;
    if (tid < NEXP) tc[tid] = g_tcol[tid];
    __syncthreads();
    const int lane = tid & 31;
    const int w = tid >> 5;
    const int row = blockIdx.x * 8 + w;

    float v0 = lg[row * NEXP + lane];
    float v1 = lg[row * NEXP + 32 + lane];
    float m0 = (v0 > tc[lane])      ? v0 : HIGH_NEG;
    float m1 = (v1 > tc[lane + 32]) ? v1 : HIGH_NEG;

    float a = fmaxf(m0, m1), b = fminf(m0, m1), c = -3.402823466e38f;
#pragma unroll
    for (int off = 16; off > 0; off >>= 1) {
        float a2 = __shfl_xor_sync(0xffffffffu, a, off);
        float b2 = __shfl_xor_sync(0xffffffffu, b, off);
        float c2 = __shfl_xor_sync(0xffffffffu, c, off);
        float o1, o2, o3;
        if (a >= a2) {
            o1 = a;
            if (b >= a2) { o2 = b;  o3 = fmaxf(c, a2); }
            else         { o2 = a2; o3 = fmaxf(b, b2); }
        } else {
            o1 = a2;
            if (b2 >= a) { o2 = b2; o3 = fmaxf(c2, a); }
            else         { o2 = a;  o3 = fmaxf(b, b2); }
        }
        a = o1; b = o2; c = o3;
    }
    float thr = c + 0.03125f * (b - c);
    float w0 = (m0 > thr) ? m0 : HIGH_NEG;
    float w1 = (m1 > thr) ? m1 : HIGH_NEG;
    float M = (a > thr) ? a : HIGH_NEG;

    float e0 = expf(w0 - M);
    float e1 = expf(w1 - M);
    float ssum = e0 + e1;
#pragma unroll
    for (int off = 16; off > 0; off >>= 1)
        ssum += __shfl_xor_sync(0xffffffffu, ssum, off);

    lg[row * NEXP + lane]      = e0 / ssum;
    lg[row * NEXP + 32 + lane] = e1 / ssum;
}

// ---------------- launch ----------------
extern "C" void kernel_launch(void* const* d_in, const int* in_sizes, int n_in,
                              void* d_out, int out_size) {
    const float *x = nullptr, *noise = nullptr, *W = nullptr, *bias = nullptr;
    for (int i = 0; i < n_in; i++) {
        switch (in_sizes[i]) {
            case NROWS * KDIM: x     = (const float*)d_in[i]; break;
            case NROWS * NEXP: noise = (const float*)d_in[i]; break;
            case NEXP * KDIM:  W     = (const float*)d_in[i]; break;
            case NEXP:         bias  = (const float*)d_in[i]; break;
            default: break;
        }
    }
    float* out = (float*)d_out;
    const int n4 = NROWS * NEXP / 4;

    cudaFuncSetAttribute(gemm_mma, cudaFuncAttributeMaxDynamicSharedMemorySize, SMEM_TOTAL);

    zero_hist1<<<NEXP * NBINS / 4 / 256, 256>>>();          // idx 0
    w_convert<<<NEXP * KDIM / 256, 256>>>(W);               // idx 1
    init_small<<<1, 64>>>();                                // idx 2
    gemm_mma<<<NROWS / BM, 256, SMEM_TOTAL>>>(x, bias, noise, out);  // idx 3 (profiled)
    find_buckets<<<NEXP, 256>>>();                          // idx 4
    collect_pass<<<4096, 256>>>((const float4*)out, n4);    // idx 5
    select_kernel<<<NEXP, 256>>>();                         // idx 6
    row_kernel<<<NROWS / 8, 256>>>(out);                    // idx 7
}